// round 5
// baseline (speedup 1.0000x reference)
#include <cuda_runtime.h>
#include <math.h>

// Problem constants (fixed by reference setup_inputs)
#define BB 2
#define CC 64
#define DD 64
#define NN 8192
#define HW 1024
#define TT 8

// Scratch (static device arrays: allowed; no allocation)
__device__ float g_qt[BB * DD * NN];   // [b][d][n], pre-scaled by 1/8
__device__ float g_kt[BB * DD * NN];   // [b][d][n]
__device__ float g_v [BB * NN * DD];   // [b][n][d]
__device__ float g_o [BB * NN * DD];   // [b][n][d]

// ---------------------------------------------------------------------------
// Projection: q/k/v = W @ x + b  (1x1x1 conv == channelwise linear)
// grid = B * (N/128) CTAs, 256 threads
// ---------------------------------------------------------------------------
#define PROJ_SMEM_FLOATS (64*128 + 3*64*64 + 3*64)

__global__ __launch_bounds__(256) void proj_kernel(
    const float* __restrict__ x,
    const float* __restrict__ wq, const float* __restrict__ bq,
    const float* __restrict__ wk, const float* __restrict__ bk,
    const float* __restrict__ wv, const float* __restrict__ bv)
{
    extern __shared__ float sm[];
    float* sx  = sm;               // [64 c][128 n]
    float* swt = sm + 64*128;      // [3][c][d] transposed weights
    float* sb  = swt + 3*64*64;    // [3][64]

    const int tid = threadIdx.x;
    const int bx  = blockIdx.x;
    const int b   = bx >> 6;
    const int n0  = (bx & 63) * 128;

    // load x tile (coalesced)
    const float4* xg  = reinterpret_cast<const float4*>(x);
    float4*       sx4 = reinterpret_cast<float4*>(sx);
    for (int i4 = tid; i4 < 64*32; i4 += 256) {
        int c = i4 >> 5, c4 = i4 & 31;
        sx4[i4] = xg[(b*64 + c)*2048 + (n0 >> 2) + c4];
    }
    // load weights transposed into smem [c][d]
    const float* ws[3] = {wq, wk, wv};
    const float* bs[3] = {bq, bk, bv};
#pragma unroll
    for (int p = 0; p < 3; p++) {
        for (int i = tid; i < 64*64; i += 256) {
            int d = i >> 6, c = i & 63;
            swt[p*4096 + c*64 + d] = ws[p][i];
        }
        if (tid < 64) sb[p*64 + tid] = bs[p][tid];
    }
    __syncthreads();

    const int tr = tid >> 4, tc = tid & 15;
    const int nl0 = tr * 8, dd0 = tc * 4;

#pragma unroll
    for (int p = 0; p < 3; p++) {
        float acc[8][4];
#pragma unroll
        for (int i = 0; i < 8; i++)
#pragma unroll
            for (int j = 0; j < 4; j++) acc[i][j] = 0.f;

        const float* W = swt + p*4096;
        for (int c = 0; c < 64; c++) {
            float4 w4 = reinterpret_cast<const float4*>(W + c*64)[tc];
            float4 xa = sx4[c*32 + 2*tr];
            float4 xb = sx4[c*32 + 2*tr + 1];
            float xv[8] = {xa.x,xa.y,xa.z,xa.w, xb.x,xb.y,xb.z,xb.w};
            float wv4[4] = {w4.x,w4.y,w4.z,w4.w};
#pragma unroll
            for (int i = 0; i < 8; i++)
#pragma unroll
                for (int j = 0; j < 4; j++) acc[i][j] += xv[i] * wv4[j];
        }
        float bbv[4];
#pragma unroll
        for (int j = 0; j < 4; j++) bbv[j] = sb[p*64 + dd0 + j];

        if (p == 0) {
            // q, scaled by 1/sqrt(64) = 0.125, stored transposed [b][d][n]
#pragma unroll
            for (int j = 0; j < 4; j++) {
                int dd = dd0 + j;
                float* dst = g_qt + ((size_t)(b*64 + dd))*NN + n0 + nl0;
#pragma unroll
                for (int i = 0; i < 8; i++) dst[i] = (acc[i][j] + bbv[j]) * 0.125f;
            }
        } else if (p == 1) {
#pragma unroll
            for (int j = 0; j < 4; j++) {
                int dd = dd0 + j;
                float* dst = g_kt + ((size_t)(b*64 + dd))*NN + n0 + nl0;
#pragma unroll
                for (int i = 0; i < 8; i++) dst[i] = acc[i][j] + bbv[j];
            }
        } else {
            float4* gv4 = reinterpret_cast<float4*>(g_v);
#pragma unroll
            for (int i = 0; i < 8; i++) {
                float4 o4 = make_float4(acc[i][0]+bbv[0], acc[i][1]+bbv[1],
                                        acc[i][2]+bbv[2], acc[i][3]+bbv[3]);
                gv4[((size_t)(b*NN) + n0 + nl0 + i)*16 + tc] = o4;
            }
        }
    }
}

// ---------------------------------------------------------------------------
// Flash attention, fp32, online softmax.
// grid = B*64 CTAs (q-tile BM=128), 256 threads, BN=64 key tile.
// ---------------------------------------------------------------------------
#define SPSTRIDE 68   // padded row stride of S/P (floats)
#define FLASH_SMEM_FLOATS (8192 + 4096 + 4096 + 128*SPSTRIDE + 128*3 + 256*2)

__global__ __launch_bounds__(256, 1) void flash_kernel()
{
    extern __shared__ float sm[];
    float* sQt   = sm;               // [64 d][128 r]
    float* sKt   = sQt + 8192;       // [64 d][64 m]
    float* sV    = sKt + 4096;       // [64 m][64 d]
    float* sP    = sV  + 4096;       // [128 r][68]
    float* sM    = sP  + 128*SPSTRIDE;
    float* sL    = sM  + 128;
    float* sF    = sL  + 128;
    float* sPmax = sF  + 128;        // [2][128]
    float* sPsum = sPmax + 256;      // [2][128]

    float4* sQt4 = reinterpret_cast<float4*>(sQt);
    float4* sKt4 = reinterpret_cast<float4*>(sKt);
    float4* sV4  = reinterpret_cast<float4*>(sV);
    float4* sP4  = reinterpret_cast<float4*>(sP);   // row stride 17 float4

    const int tid = threadIdx.x;
    const int b   = blockIdx.x >> 6;
    const int q0  = (blockIdx.x & 63) * 128;

    const float4* gqt4 = reinterpret_cast<const float4*>(g_qt);
    const float4* gkt4 = reinterpret_cast<const float4*>(g_kt);
    const float4* gv4  = reinterpret_cast<const float4*>(g_v);

    // Load Q tile (transposed layout, coalesced)
    for (int i4 = tid; i4 < 64*32; i4 += 256) {
        int dd = i4 >> 5, c4 = i4 & 31;
        sQt4[i4] = gqt4[(b*64 + dd)*2048 + (q0 >> 2) + c4];
    }
    if (tid < 128) { sM[tid] = -INFINITY; sL[tid] = 0.f; }

    const int tr = tid >> 4, tc = tid & 15;
    const int r0 = tr * 8;

    float of[8][4];
#pragma unroll
    for (int i = 0; i < 8; i++)
#pragma unroll
        for (int j = 0; j < 4; j++) of[i][j] = 0.f;

    for (int kt = 0; kt < 128; kt++) {
        const int k0 = kt * 64;
        __syncthreads();  // previous PV done before overwriting K/V tiles
        for (int i4 = tid; i4 < 64*16; i4 += 256) {
            int dd = i4 >> 4, c4 = i4 & 15;
            sKt4[i4] = gkt4[(b*64 + dd)*2048 + (k0 >> 2) + c4];
        }
        for (int i4 = tid; i4 < 64*16; i4 += 256) {
            int m = i4 >> 4, d4 = i4 & 15;
            sV4[i4] = gv4[((size_t)(b*NN) + k0 + m)*16 + d4];
        }
        __syncthreads();

        // S = (Qt)^T * Kt  — 8x4 micro-tile per thread
        float sfr[8][4];
#pragma unroll
        for (int i = 0; i < 8; i++)
#pragma unroll
            for (int j = 0; j < 4; j++) sfr[i][j] = 0.f;

#pragma unroll 4
        for (int dd = 0; dd < 64; dd++) {
            float4 k4 = sKt4[dd*16 + tc];
            float4 qa = sQt4[dd*32 + 2*tr];
            float4 qb = sQt4[dd*32 + 2*tr + 1];
            float qv[8] = {qa.x,qa.y,qa.z,qa.w, qb.x,qb.y,qb.z,qb.w};
            float kv[4] = {k4.x,k4.y,k4.z,k4.w};
#pragma unroll
            for (int i = 0; i < 8; i++)
#pragma unroll
                for (int j = 0; j < 4; j++) sfr[i][j] += qv[i] * kv[j];
        }
#pragma unroll
        for (int i = 0; i < 8; i++)
            sP4[(r0 + i)*17 + tc] = make_float4(sfr[i][0], sfr[i][1], sfr[i][2], sfr[i][3]);
        __syncthreads();

        // partial row max (2 threads per row, 32 cols each)
        {
            int h = tid >> 7, r = tid & 127;
            const float4* row = sP4 + r*17 + h*8;
            float pm = -INFINITY;
#pragma unroll
            for (int i = 0; i < 8; i++) {
                float4 v = row[i];
                pm = fmaxf(pm, fmaxf(fmaxf(v.x, v.y), fmaxf(v.z, v.w)));
            }
            sPmax[h*128 + r] = pm;
        }
        __syncthreads();
        if (tid < 128) {
            float mo = sM[tid];
            float mn = fmaxf(mo, fmaxf(sPmax[tid], sPmax[128 + tid]));
            sF[tid] = __expf(mo - mn);
            sM[tid] = mn;
        }
        __syncthreads();

        // exp pass + partial sums, write P in place
        {
            int h = tid >> 7, r = tid & 127;
            float mn = sM[r];
            float4* row = sP4 + r*17 + h*8;
            float ps = 0.f;
#pragma unroll
            for (int i = 0; i < 8; i++) {
                float4 v = row[i];
                v.x = __expf(v.x - mn);
                v.y = __expf(v.y - mn);
                v.z = __expf(v.z - mn);
                v.w = __expf(v.w - mn);
                ps += v.x + v.y + v.z + v.w;
                row[i] = v;
            }
            sPsum[h*128 + r] = ps;
        }
        // rescale O accumulator by row factor
#pragma unroll
        for (int i = 0; i < 8; i++) {
            float f = sF[r0 + i];
#pragma unroll
            for (int j = 0; j < 4; j++) of[i][j] *= f;
        }
        __syncthreads();
        if (tid < 128) sL[tid] = sL[tid] * sF[tid] + sPsum[tid] + sPsum[128 + tid];

        // O += P * V  (contraction over m, 4 m's per step)
#pragma unroll
        for (int m4 = 0; m4 < 16; m4++) {
            float4 va = sV4[(m4*4 + 0)*16 + tc];
            float4 vb = sV4[(m4*4 + 1)*16 + tc];
            float4 vc = sV4[(m4*4 + 2)*16 + tc];
            float4 vd = sV4[(m4*4 + 3)*16 + tc];
            float vm[4][4] = {{va.x,va.y,va.z,va.w},
                              {vb.x,vb.y,vb.z,vb.w},
                              {vc.x,vc.y,vc.z,vc.w},
                              {vd.x,vd.y,vd.z,vd.w}};
#pragma unroll
            for (int i = 0; i < 8; i++) {
                float4 p4 = sP4[(r0 + i)*17 + m4];
                float pm[4] = {p4.x, p4.y, p4.z, p4.w};
#pragma unroll
                for (int k = 0; k < 4; k++)
#pragma unroll
                    for (int j = 0; j < 4; j++) of[i][j] += pm[k] * vm[k][j];
            }
        }
    }
    __syncthreads();

    float4* go4 = reinterpret_cast<float4*>(g_o);
#pragma unroll
    for (int i = 0; i < 8; i++) {
        int r = r0 + i;
        float inv = 1.0f / sL[r];
        go4[((size_t)(b*NN) + q0 + r)*16 + tc] =
            make_float4(of[i][0]*inv, of[i][1]*inv, of[i][2]*inv, of[i][3]*inv);
    }
}

// ---------------------------------------------------------------------------
// Final reduction: out[b][d][hw] = sum_t o[b][t*HW+hw][d]   (deterministic)
// ---------------------------------------------------------------------------
__global__ __launch_bounds__(256) void reduce_kernel(float* __restrict__ out)
{
    int idx = blockIdx.x * 256 + threadIdx.x;
    if (idx >= BB * DD * HW) return;
    int b   = idx / (DD * HW);
    int rem = idx % (DD * HW);
    int d   = rem / HW;
    int hw  = rem % HW;
    float s = 0.f;
#pragma unroll
    for (int t = 0; t < TT; t++)
        s += g_o[((size_t)(b*NN) + t*HW + hw)*DD + d];
    out[idx] = s;
}

// ---------------------------------------------------------------------------
extern "C" void kernel_launch(void* const* d_in, const int* in_sizes, int n_in,
                              void* d_out, int out_size)
{
    (void)in_sizes; (void)n_in; (void)out_size;
    const float* x  = (const float*)d_in[0];
    const float* wq = (const float*)d_in[1];
    const float* bq = (const float*)d_in[2];
    const float* wk = (const float*)d_in[3];
    const float* bk = (const float*)d_in[4];
    const float* wv = (const float*)d_in[5];
    const float* bv = (const float*)d_in[6];
    float* out = (float*)d_out;

    const int proj_smem  = PROJ_SMEM_FLOATS  * sizeof(float);   // ~83 KB
    const int flash_smem = FLASH_SMEM_FLOATS * sizeof(float);   // ~104 KB
    cudaFuncSetAttribute(proj_kernel,  cudaFuncAttributeMaxDynamicSharedMemorySize, proj_smem);
    cudaFuncSetAttribute(flash_kernel, cudaFuncAttributeMaxDynamicSharedMemorySize, flash_smem);

    proj_kernel<<<BB * (NN/128), 256, proj_smem>>>(x, wq, bq, wk, bk, wv, bv);
    flash_kernel<<<BB * (NN/128), 256, flash_smem>>>();
    reduce_kernel<<<(BB*DD*HW + 255)/256, 256>>>(out);
}